// round 13
// baseline (speedup 1.0000x reference)
#include <cuda_runtime.h>
#include <cuda_fp16.h>
#include <math.h>

#define N_NODES   100000
#define N_EDGES   1600000
#define N_GRAPHS  1024
#define HDIM      64
#define EPSV      1e-7f
#define LOG2E     1.4426950408889634f
#define SHL2      57.707801635558536f   /* 40 * log2(e) */
#define SCAN_BLK  512
#define NSCAN     ((N_NODES + SCAN_BLK - 1) / SCAN_BLK)   // 196

typedef unsigned long long ull;

#define FLAG_AGG  (1ull << 62)
#define FLAG_INC  (1ull << 63)

// ---------------- scratch (static device globals; no allocation) -------------
// Invariants at kernel_launch entry (zero at load; restored by head_kernel):
//   g_deg[*] == 0,  g_lb[*] == 0
__device__ float g_h0[N_NODES * HDIM];
__device__ float g_h1[N_NODES * HDIM];
__device__ float g_agg[N_NODES * HDIM];
__device__ float g_pool[N_GRAPHS * HDIM];
__device__ float g_cnt[N_GRAPHS];
__device__ int   g_deg[N_NODES];
__device__ int   g_off[N_NODES];
__device__ int   g_cursor[N_NODES];
__device__ ull   g_lb[NSCAN];
__device__ int   g_src_s[N_EDGES];
__device__ unsigned g_ea_p[(size_t)N_EDGES * 32];   // dst-sorted fp16 messages (205 MB)

__device__ __forceinline__ void red4(float* p, float a, float b, float c, float d) {
    asm volatile("red.global.add.v4.f32 [%0], {%1,%2,%3,%4};"
                 :: "l"(p), "f"(a), "f"(b), "f"(c), "f"(d) : "memory");
}
__device__ __forceinline__ ull pack2(float x, float y) {
    ull r; asm("mov.b64 %0, {%1, %2};" : "=l"(r) : "f"(x), "f"(y)); return r;
}
__device__ __forceinline__ void unpack2(float& x, float& y, ull v) {
    asm("mov.b64 {%0, %1}, %2;" : "=f"(x), "=f"(y) : "l"(v));
}
__device__ __forceinline__ void fma2(ull& d, ull a, ull b) {
    asm("fma.rn.f32x2 %0, %1, %2, %0;" : "+l"(d) : "l"(a), "l"(b));
}
__device__ __forceinline__ ull fma2_3(ull a, ull b, ull c) {
    ull d; asm("fma.rn.f32x2 %0, %1, %2, %3;" : "=l"(d) : "l"(a), "l"(b), "l"(c)); return d;
}
__device__ __forceinline__ ull add2(ull a, ull b) {
    ull d; asm("add.rn.f32x2 %0, %1, %2;" : "=l"(d) : "l"(a), "l"(b)); return d;
}
__device__ __forceinline__ ull splat(float v) { return pack2(v, v); }
__device__ __forceinline__ ull ld_cg64(const ull* p) {
    ull v; asm volatile("ld.global.cg.b64 %0, [%1];" : "=l"(v) : "l"(p)); return v;
}

// ------- h0 = x @ node_W + node_b (16->64), fused hist + scratch zeroing ------
__global__ void __launch_bounds__(256) input_proj(const float* __restrict__ x,
                                                  const float* __restrict__ W,
                                                  const float* __restrict__ b,
                                                  const int* __restrict__ edst) {
    __shared__ float4 sW[256];
    __shared__ float4 sb[16];
    int tid = threadIdx.x;
    sW[tid] = ((const float4*)W)[tid];
    if (tid < 16) sb[tid] = ((const float4*)b)[tid];
    __syncthreads();

    int t = blockIdx.x * 256 + tid;   // grid covers exactly N_EDGES threads
    atomicAdd(&g_deg[__ldg(edst + t)], 1);     // g_deg zero at entry (invariant)
    if (t < N_GRAPHS * HDIM) g_pool[t] = 0.0f;
    if (t < N_GRAPHS) g_cnt[t] = 0.0f;

    int n = t >> 4, g = t & 15;
    if (n >= N_NODES) return;
    const float4* xr = (const float4*)(x + n * 16);
    float4 x0 = xr[0], x1 = xr[1], x2 = xr[2], x3 = xr[3];
    float4 acc = sb[g];
#define ISTEP(av, kk) { float4 w = sW[(kk)*16 + g]; \
    acc.x = fmaf(av, w.x, acc.x); acc.y = fmaf(av, w.y, acc.y); \
    acc.z = fmaf(av, w.z, acc.z); acc.w = fmaf(av, w.w, acc.w); }
    ISTEP(x0.x, 0)  ISTEP(x0.y, 1)  ISTEP(x0.z, 2)  ISTEP(x0.w, 3)
    ISTEP(x1.x, 4)  ISTEP(x1.y, 5)  ISTEP(x1.z, 6)  ISTEP(x1.w, 7)
    ISTEP(x2.x, 8)  ISTEP(x2.y, 9)  ISTEP(x2.z, 10) ISTEP(x2.w, 11)
    ISTEP(x3.x, 12) ISTEP(x3.y, 13) ISTEP(x3.z, 14) ISTEP(x3.w, 15)
#undef ISTEP
    ((float4*)(g_h0 + (size_t)n * HDIM))[g] = acc;
}

// ------ single-pass scan (decoupled lookback); also cursor init + g_cnt -------
__global__ void __launch_bounds__(SCAN_BLK) scan_lb(const int* __restrict__ batch) {
    __shared__ int wsum[SCAN_BLK / 32];
    __shared__ int sExcl;
    int bid = blockIdx.x;
    int d = bid * SCAN_BLK + threadIdx.x;
    int v = (d < N_NODES) ? g_deg[d] : 0;
    int lane = threadIdx.x & 31, w = threadIdx.x >> 5;

    int inc = v;
#pragma unroll
    for (int o = 1; o < 32; o <<= 1) {
        int t = __shfl_up_sync(0xffffffffu, inc, o);
        if (lane >= o) inc += t;
    }
    if (lane == 31) wsum[w] = inc;
    __syncthreads();
    if (w == 0) {
        int s = (lane < SCAN_BLK / 32) ? wsum[lane] : 0;
#pragma unroll
        for (int o = 1; o < 16; o <<= 1) {
            int t = __shfl_up_sync(0xffffffffu, s, o);
            if (lane >= o) s += t;
        }
        if (lane < SCAN_BLK / 32) wsum[lane] = s;
    }
    __syncthreads();
    int base = (w > 0) ? wsum[w - 1] : 0;
    int total = wsum[SCAN_BLK / 32 - 1];

    if (threadIdx.x == 0) {
        ull pub = (bid == 0) ? (FLAG_INC | (unsigned)total)
                             : (FLAG_AGG | (unsigned)total);
        __threadfence();
        atomicExch(&g_lb[bid], pub);
        if (bid == 0) sExcl = 0;
    }
    if (bid > 0 && w == 0) {
        int excl = 0;
        int offset = bid - 1;
        while (true) {
            int idx = offset - lane;
            ull val = (idx >= 0) ? ld_cg64(&g_lb[idx]) : FLAG_INC;
            while (__any_sync(0xffffffffu, val == 0ull))
                val = (idx >= 0) ? ld_cg64(&g_lb[idx]) : FLAG_INC;
            unsigned f2 = __ballot_sync(0xffffffffu, (val & FLAG_INC) != 0ull);
            int cv = (int)(unsigned)(val & 0xffffffffull);
            if (f2) {
                int first = __ffs(f2) - 1;
                int contrib = (lane <= first) ? cv : 0;
#pragma unroll
                for (int o = 16; o; o >>= 1) contrib += __shfl_xor_sync(0xffffffffu, contrib, o);
                excl += contrib;
                break;
            } else {
                int contrib = cv;
#pragma unroll
                for (int o = 16; o; o >>= 1) contrib += __shfl_xor_sync(0xffffffffu, contrib, o);
                excl += contrib;
                offset -= 32;
            }
        }
        if (lane == 0) {
            sExcl = excl;
            __threadfence();
            atomicExch(&g_lb[bid], FLAG_INC | (unsigned)(excl + total));
        }
    }
    __syncthreads();

    int bg = (d < N_NODES) ? __ldg(batch + d) : -1;
    if (d < N_NODES) {
        int o = sExcl + base + inc - v;
        g_off[d] = o;
        g_cursor[d] = o;
    }
    unsigned m = __match_any_sync(0xffffffffu, bg);
    if (bg >= 0 && (int)(__ffs(m) - 1) == lane)
        atomicAdd(&g_cnt[bg], (float)__popc(m));
}

// ----- project + scatter: ea_p[pos] = half2(edge_attr[e] @ eW + eb), dst-sorted
__global__ void __launch_bounds__(256) project_scatter(const float* __restrict__ edge_attr,
                                                       const int* __restrict__ esrc,
                                                       const int* __restrict__ edst,
                                                       const float* __restrict__ eW,
                                                       const float* __restrict__ eb) {
    int lane = threadIdx.x & 31;
    int w = threadIdx.x >> 5;
    int ebase = (blockIdx.x * 8 + w) * 8;     // grid = N_EDGES/64 = 25000 exact

    ull W0 = __ldg((const ull*)(eW + 0 * 64) + lane);
    ull W1 = __ldg((const ull*)(eW + 1 * 64) + lane);
    ull W2 = __ldg((const ull*)(eW + 2 * 64) + lane);
    ull W3 = __ldg((const ull*)(eW + 3 * 64) + lane);
    ull W4 = __ldg((const ull*)(eW + 4 * 64) + lane);
    ull W5 = __ldg((const ull*)(eW + 5 * 64) + lane);
    ull W6 = __ldg((const ull*)(eW + 6 * 64) + lane);
    ull W7 = __ldg((const ull*)(eW + 7 * 64) + lane);
    ull BB = __ldg((const ull*)eb + lane);

    int mysrc = 0, mypos = 0;
    if (lane < 8) {
        int e = ebase + lane;
        mysrc = __ldg(esrc + e);
        int d = __ldg(edst + e);
        mypos = atomicAdd(&g_cursor[d], 1);
    }

#pragma unroll
    for (int j = 0; j < 8; j++) {
        const float4* ap = (const float4*)(edge_attr + (size_t)(ebase + j) * 8);
        float4 a0 = __ldg(ap), a1 = __ldg(ap + 1);
        ull E = fma2_3(splat(a0.x), W0, BB);
        fma2(E, splat(a0.y), W1);
        fma2(E, splat(a0.z), W2);
        fma2(E, splat(a0.w), W3);
        fma2(E, splat(a1.x), W4);
        fma2(E, splat(a1.y), W5);
        fma2(E, splat(a1.z), W6);
        fma2(E, splat(a1.w), W7);
        float t0, t1; unpack2(t0, t1, E);
        __half2 hh = __floats2half2_rn(t0, t1);
        int pos = __shfl_sync(0xffffffffu, mypos, j);
        g_ea_p[(size_t)pos * 32 + lane] = *(unsigned*)&hh;
    }
    if (lane < 8) g_src_s[mypos] = mysrc;
}

// ---- per-dst aggregation: warp/dst, lane-split edge pairs (R9 version) --------
__global__ void __launch_bounds__(256) agg_pass(int cur) {
    int lane = threadIdx.x & 31;
    int half = lane >> 4;
    int fl = lane & 15;
    int d = blockIdx.x * 8 + (threadIdx.x >> 5);   // grid 12500 exact
    const float* h = cur ? g_h1 : g_h0;
    const ull* eap = (const ull*)g_ea_p;

    const ull L2E2 = splat(LOG2E);
    const ull C2   = splat(-SHL2);

    int start = g_off[d];
    int end = start + g_deg[d];
    ull DEN0 = 0ull, DEN1 = 0ull, NUM0 = 0ull, NUM1 = 0ull;

#define PBODY(EAu, HA, HB) { \
    unsigned lo_ = (unsigned)(EAu), hi_ = (unsigned)((EAu) >> 32); \
    float2 ea0 = __half22float2(*(__half2*)&lo_); \
    float2 ea1 = __half22float2(*(__half2*)&hi_); \
    ull E0 = add2(pack2(ea0.x, ea0.y), (HA)); \
    ull E1 = add2(pack2(ea1.x, ea1.y), (HB)); \
    float t0, t1, t2, t3; unpack2(t0, t1, E0); unpack2(t2, t3, E1); \
    float m0 = fmaxf(t0, 0.f) + EPSV, m1 = fmaxf(t1, 0.f) + EPSV; \
    float m2 = fmaxf(t2, 0.f) + EPSV, m3 = fmaxf(t3, 0.f) + EPSV; \
    ull M0 = pack2(m0, m1), M1 = pack2(m2, m3); \
    ull A0 = fma2_3(M0, L2E2, C2), A1 = fma2_3(M1, L2E2, C2); \
    float a0v, a1v, a2v, a3v; unpack2(a0v, a1v, A0); unpack2(a2v, a3v, A1); \
    ull X0 = pack2(exp2f(a0v), exp2f(a1v)); \
    ull X1 = pack2(exp2f(a2v), exp2f(a3v)); \
    DEN0 = add2(DEN0, X0); DEN1 = add2(DEN1, X1); \
    fma2(NUM0, M0, X0); fma2(NUM1, M1, X1); }

    int i = start;
    for (; i + 4 <= end; i += 4) {
        int sA = __ldg(g_src_s + i + half);
        int sB = __ldg(g_src_s + i + 2 + half);
        ull EA0 = __ldg(eap + (size_t)(i + half) * 16 + fl);
        ull EA1 = __ldg(eap + (size_t)(i + 2 + half) * 16 + fl);
        ulonglong2 HA = __ldg((const ulonglong2*)(h + (size_t)sA * HDIM + 4 * fl));
        ulonglong2 HB = __ldg((const ulonglong2*)(h + (size_t)sB * HDIM + 4 * fl));
        PBODY(EA0, HA.x, HA.y)
        PBODY(EA1, HB.x, HB.y)
    }
    for (; i + 2 <= end; i += 2) {
        int s = __ldg(g_src_s + i + half);
        ull EA = __ldg(eap + (size_t)(i + half) * 16 + fl);
        ulonglong2 HV = __ldg((const ulonglong2*)(h + (size_t)s * HDIM + 4 * fl));
        PBODY(EA, HV.x, HV.y)
    }
    if (i < end) {
        int s = __ldg(g_src_s + i);
        ull EA = __ldg(eap + (size_t)i * 16 + fl);
        ulonglong2 HV = __ldg((const ulonglong2*)(h + (size_t)s * HDIM + 4 * fl));
        if (half == 0) { PBODY(EA, HV.x, HV.y) }
    }
#undef PBODY

    DEN0 = add2(DEN0, __shfl_xor_sync(0xffffffffu, DEN0, 16));
    DEN1 = add2(DEN1, __shfl_xor_sync(0xffffffffu, DEN1, 16));
    NUM0 = add2(NUM0, __shfl_xor_sync(0xffffffffu, NUM0, 16));
    NUM1 = add2(NUM1, __shfl_xor_sync(0xffffffffu, NUM1, 16));

    if (half == 0) {
        float d0, d1, d2, d3, n0, n1, n2, n3;
        unpack2(d0, d1, DEN0); unpack2(d2, d3, DEN1);
        unpack2(n0, n1, NUM0); unpack2(n2, n3, NUM1);
        float4 o = make_float4(n0 / fmaxf(d0, 1e-16f), n1 / fmaxf(d1, 1e-16f),
                               n2 / fmaxf(d2, 1e-16f), n3 / fmaxf(d3, 1e-16f));
        *(float4*)(g_agg + (size_t)d * HDIM + 4 * fl) = o;
    }
}

// ---- node MLP v2: weights via LDG (L1-resident), smem only sX+sH, 3 CTAs/SM ---
#define SX_STRIDE 68
#define SH_STRIDE 68
#define SMEM_FLOATS (8704 + 4352)   // 13056 floats = 52224 bytes

__global__ void __launch_bounds__(256, 3) node_mlp(int cur, int last,
                                                   const float* __restrict__ W1,
                                                   const float* __restrict__ b1,
                                                   const float* __restrict__ W2,
                                                   const float* __restrict__ b2,
                                                   const int* __restrict__ batch) {
    extern __shared__ float sm[];
    float* sH = sm;            // [128][68]
    float* sX = sm + 8704;     // [64][68]

    int tid = threadIdx.x;
    int base = blockIdx.x * 64;
    const float* h_in  = cur ? g_h1 : g_h0;
    float*       h_out = cur ? g_h0 : g_h1;

    for (int idx = tid; idx < 64 * 64; idx += 256) {
        int n = idx >> 6, f = idx & 63;
        int gn = base + n;
        float v = 0.0f;
        if (gn < N_NODES)
            v = h_in[(size_t)gn * HDIM + f] + g_agg[(size_t)gn * HDIM + f];
        sX[f * SX_STRIDE + n] = v;
    }
    __syncthreads();

    int nodeg = tid & 15;   // 4 nodes
    int hidg  = tid >> 4;   // 8 hidden = 4 packed pairs

    // ---- phase 1: hid = relu(x @ W1 + b1); W1 read via LDG (L1-resident) ----
    ull acc[4][4];
    {
        float4 ba = __ldg((const float4*)&b1[hidg * 8]);
        float4 bbv = __ldg((const float4*)&b1[hidg * 8 + 4]);
        ull p0 = pack2(ba.x, ba.y), p1 = pack2(ba.z, ba.w);
        ull p2 = pack2(bbv.x, bbv.y), p3 = pack2(bbv.z, bbv.w);
#pragma unroll
        for (int n = 0; n < 4; n++) { acc[n][0] = p0; acc[n][1] = p1; acc[n][2] = p2; acc[n][3] = p3; }
    }
#pragma unroll 4
    for (int k = 0; k < 64; k++) {
        float4 xv = *(const float4*)&sX[k * SX_STRIDE + nodeg * 4];
        ulonglong2 wA = __ldg((const ulonglong2*)&W1[k * 128 + hidg * 8]);
        ulonglong2 wB = __ldg((const ulonglong2*)&W1[k * 128 + hidg * 8 + 4]);
        float xs[4] = { xv.x, xv.y, xv.z, xv.w };
#pragma unroll
        for (int n = 0; n < 4; n++) {
            ull xd = pack2(xs[n], xs[n]);
            fma2(acc[n][0], xd, wA.x);
            fma2(acc[n][1], xd, wA.y);
            fma2(acc[n][2], xd, wB.x);
            fma2(acc[n][3], xd, wB.y);
        }
    }
#pragma unroll
    for (int p = 0; p < 4; p++) {
        float lo[4], hi[4];
#pragma unroll
        for (int n = 0; n < 4; n++) unpack2(lo[n], hi[n], acc[n][p]);
        *(float4*)&sH[(hidg * 8 + 2 * p) * SH_STRIDE + nodeg * 4] =
            make_float4(fmaxf(lo[0], 0.f), fmaxf(lo[1], 0.f), fmaxf(lo[2], 0.f), fmaxf(lo[3], 0.f));
        *(float4*)&sH[(hidg * 8 + 2 * p + 1) * SH_STRIDE + nodeg * 4] =
            make_float4(fmaxf(hi[0], 0.f), fmaxf(hi[1], 0.f), fmaxf(hi[2], 0.f), fmaxf(hi[3], 0.f));
    }
    __syncthreads();

    // ---- phase 2: out = relu(hid @ W2 + b2); W2 via LDG ----
    int outg = tid >> 4;
    ull a2[4][2];
    {
        float4 bv = __ldg((const float4*)&b2[outg * 4]);
        ull p0 = pack2(bv.x, bv.y), p1 = pack2(bv.z, bv.w);
#pragma unroll
        for (int n = 0; n < 4; n++) { a2[n][0] = p0; a2[n][1] = p1; }
    }
#pragma unroll 4
    for (int k = 0; k < 128; k++) {
        float4 hv = *(const float4*)&sH[k * SH_STRIDE + nodeg * 4];
        ulonglong2 wp = __ldg((const ulonglong2*)&W2[k * 64 + outg * 4]);
        float hs[4] = { hv.x, hv.y, hv.z, hv.w };
#pragma unroll
        for (int n = 0; n < 4; n++) {
            ull xd = pack2(hs[n], hs[n]);
            fma2(a2[n][0], xd, wp.x);
            fma2(a2[n][1], xd, wp.y);
        }
    }
#pragma unroll
    for (int n = 0; n < 4; n++) {
        int gn = base + nodeg * 4 + n;
        if (gn < N_NODES) {
            float r0, r1, r2, r3;
            unpack2(r0, r1, a2[n][0]);
            unpack2(r2, r3, a2[n][1]);
            r0 = fmaxf(r0, 0.f); r1 = fmaxf(r1, 0.f);
            r2 = fmaxf(r2, 0.f); r3 = fmaxf(r3, 0.f);
            if (last) {
                int b = __ldg(batch + gn);
                red4(g_pool + (size_t)b * HDIM + outg * 4, r0, r1, r2, r3);
            } else {
                *(float4*)&h_out[(size_t)gn * HDIM + outg * 4] = make_float4(r0, r1, r2, r3);
            }
        }
    }
}

// --------- graph head (restores g_deg / g_lb invariants for next call) ---------
__global__ void __launch_bounds__(256) head_kernel(const float* __restrict__ graph_attr,
                                                   const float* __restrict__ d1W, const float* __restrict__ d1b,
                                                   const float* __restrict__ d2W, const float* __restrict__ d2b,
                                                   const float* __restrict__ oW,  const float* __restrict__ ob,
                                                   float* __restrict__ out) {
    int t = blockIdx.x * 256 + threadIdx.x;
    for (int i = t; i < N_NODES; i += (N_GRAPHS * 32)) g_deg[i] = 0;
    if (t < NSCAN) g_lb[t] = 0ull;

    int g = t >> 5, lane = t & 31;
    if (g >= N_GRAPHS) return;
    float cnt = fmaxf(g_cnt[g], 1.0f);
    float p0 = g_pool[g * HDIM + lane] / cnt;
    float p1 = g_pool[g * HDIM + 32 + lane] / cnt;
    float ga = (lane < 10) ? graph_attr[g * 10 + lane] : 0.0f;

    float a = d1b[lane];
#pragma unroll
    for (int k = 0; k < 32; k++) a = fmaf(__shfl_sync(0xffffffffu, p0, k), d1W[k * 32 + lane], a);
#pragma unroll
    for (int k = 0; k < 32; k++) a = fmaf(__shfl_sync(0xffffffffu, p1, k), d1W[(32 + k) * 32 + lane], a);
#pragma unroll
    for (int k = 0; k < 10; k++) a = fmaf(__shfl_sync(0xffffffffu, ga, k), d1W[(64 + k) * 32 + lane], a);
    a = fmaxf(a, 0.0f);

    float bsum = d2b[lane];
#pragma unroll
    for (int k = 0; k < 32; k++) bsum = fmaf(__shfl_sync(0xffffffffu, a, k), d2W[k * 32 + lane], bsum);
    bsum = fmaxf(bsum, 0.0f);

    float v = bsum * oW[lane];
#pragma unroll
    for (int s = 16; s > 0; s >>= 1) v += __shfl_xor_sync(0xffffffffu, v, s);
    if (lane == 0) out[g] = 1.0f / (1.0f + expf(-(v + ob[0])));
}

// ---------------- launch -------------------------------------------------------
extern "C" void kernel_launch(void* const* d_in, const int* in_sizes, int n_in,
                              void* d_out, int out_size) {
    const float* x          = (const float*)d_in[0];
    const float* edge_attr  = (const float*)d_in[1];
    const float* graph_attr = (const float*)d_in[2];
    const int*   edge_index = (const int*)d_in[3];
    const int*   batch      = (const int*)d_in[4];
    const float* node_W     = (const float*)d_in[5];
    const float* node_b     = (const float*)d_in[6];
    const float* edge_W     = (const float*)d_in[7];
    const float* edge_b     = (const float*)d_in[8];
    const float* cW1[3] = { (const float*)d_in[9],  (const float*)d_in[13], (const float*)d_in[17] };
    const float* cb1[3] = { (const float*)d_in[10], (const float*)d_in[14], (const float*)d_in[18] };
    const float* cW2[3] = { (const float*)d_in[11], (const float*)d_in[15], (const float*)d_in[19] };
    const float* cb2[3] = { (const float*)d_in[12], (const float*)d_in[16], (const float*)d_in[20] };
    const float* d1W = (const float*)d_in[21];
    const float* d1b = (const float*)d_in[22];
    const float* d2W = (const float*)d_in[23];
    const float* d2b = (const float*)d_in[24];
    const float* oW  = (const float*)d_in[25];
    const float* ob  = (const float*)d_in[26];
    const int* esrc = edge_index;
    const int* edst = edge_index + N_EDGES;
    float* out = (float*)d_out;

    const int SMEM_MLP = SMEM_FLOATS * 4;   // 52224 bytes
    cudaFuncSetAttribute((const void*)node_mlp,
                         cudaFuncAttributeMaxDynamicSharedMemorySize, SMEM_MLP);

    // 1: proj + hist + zeroing
    input_proj<<<N_EDGES / 256, 256>>>(x, node_W, node_b, edst);
    // 2: single-pass scan (+cursor init, g_cnt)
    scan_lb<<<NSCAN, SCAN_BLK>>>(batch);
    // 3: project ea once (fp16) + scatter to dst order
    project_scatter<<<N_EDGES / 64, 256>>>(edge_attr, esrc, edst, edge_W, edge_b);

    int cur = 0;
    const int NBLK_MLP = (N_NODES + 63) / 64;
    for (int c = 0; c < 3; c++) {
        // c==0: launch #4 = agg_pass (sanity A/B vs R9's 86 us)
        agg_pass<<<N_NODES / 8, 256>>>(cur);
        node_mlp<<<NBLK_MLP, 256, SMEM_MLP>>>(cur, (c == 2) ? 1 : 0,
                                              cW1[c], cb1[c], cW2[c], cb2[c], batch);
        cur ^= 1;
    }

    head_kernel<<<(N_GRAPHS * 32) / 256, 256>>>(graph_attr, d1W, d1b, d2W, d2b, oW, ob, out);
}

// round 16
// speedup vs baseline: 1.1908x; 1.1908x over previous
#include <cuda_runtime.h>
#include <cuda_fp16.h>
#include <math.h>

#define N_NODES   100000
#define N_EDGES   1600000
#define N_GRAPHS  1024
#define HDIM      64
#define EPSV      1e-7f
#define LOG2E     1.4426950408889634f
#define SHL2      57.707801635558536f   /* 40 * log2(e) */
#define SCAN_BLK  512
#define NSCAN     ((N_NODES + SCAN_BLK - 1) / SCAN_BLK)   // 196

typedef unsigned long long ull;

#define FLAG_AGG  (1ull << 62)
#define FLAG_INC  (1ull << 63)

// ---------------- scratch (static device globals; no allocation) -------------
// Invariants at kernel_launch entry (zero at load; restored by head_kernel):
//   g_deg[*] == 0,  g_lb[*] == 0
__device__ float g_h0[N_NODES * HDIM];
__device__ float g_h1[N_NODES * HDIM];
__device__ float g_agg[N_NODES * HDIM];
__device__ float g_pool[N_GRAPHS * HDIM];
__device__ float g_cnt[N_GRAPHS];
__device__ int   g_deg[N_NODES];
__device__ int   g_off[N_NODES];
__device__ int   g_cursor[N_NODES];
__device__ ull   g_lb[NSCAN];
__device__ int   g_src_s[N_EDGES];
__device__ unsigned g_ea_p[(size_t)N_EDGES * 32];   // dst-sorted fp16 messages (205 MB)

__device__ __forceinline__ void red4(float* p, float a, float b, float c, float d) {
    asm volatile("red.global.add.v4.f32 [%0], {%1,%2,%3,%4};"
                 :: "l"(p), "f"(a), "f"(b), "f"(c), "f"(d) : "memory");
}
__device__ __forceinline__ ull pack2(float x, float y) {
    ull r; asm("mov.b64 %0, {%1, %2};" : "=l"(r) : "f"(x), "f"(y)); return r;
}
__device__ __forceinline__ void unpack2(float& x, float& y, ull v) {
    asm("mov.b64 {%0, %1}, %2;" : "=f"(x), "=f"(y) : "l"(v));
}
__device__ __forceinline__ void fma2(ull& d, ull a, ull b) {
    asm("fma.rn.f32x2 %0, %1, %2, %0;" : "+l"(d) : "l"(a), "l"(b));
}
__device__ __forceinline__ ull fma2_3(ull a, ull b, ull c) {
    ull d; asm("fma.rn.f32x2 %0, %1, %2, %3;" : "=l"(d) : "l"(a), "l"(b), "l"(c)); return d;
}
__device__ __forceinline__ ull add2(ull a, ull b) {
    ull d; asm("add.rn.f32x2 %0, %1, %2;" : "=l"(d) : "l"(a), "l"(b)); return d;
}
__device__ __forceinline__ ull splat(float v) { return pack2(v, v); }
__device__ __forceinline__ ull ld_cg64(const ull* p) {
    ull v; asm volatile("ld.global.cg.b64 %0, [%1];" : "=l"(v) : "l"(p)); return v;
}

// ------- h0 = x @ node_W + node_b (16->64), fused hist + scratch zeroing ------
__global__ void __launch_bounds__(256) input_proj(const float* __restrict__ x,
                                                  const float* __restrict__ W,
                                                  const float* __restrict__ b,
                                                  const int* __restrict__ edst) {
    __shared__ float4 sW[256];
    __shared__ float4 sb[16];
    int tid = threadIdx.x;
    sW[tid] = ((const float4*)W)[tid];
    if (tid < 16) sb[tid] = ((const float4*)b)[tid];
    __syncthreads();

    int t = blockIdx.x * 256 + tid;   // grid covers exactly N_EDGES threads
    atomicAdd(&g_deg[__ldg(edst + t)], 1);     // g_deg zero at entry (invariant)
    if (t < N_GRAPHS * HDIM) g_pool[t] = 0.0f;
    if (t < N_GRAPHS) g_cnt[t] = 0.0f;

    int n = t >> 4, g = t & 15;
    if (n >= N_NODES) return;
    const float4* xr = (const float4*)(x + n * 16);
    float4 x0 = xr[0], x1 = xr[1], x2 = xr[2], x3 = xr[3];
    float4 acc = sb[g];
#define ISTEP(av, kk) { float4 w = sW[(kk)*16 + g]; \
    acc.x = fmaf(av, w.x, acc.x); acc.y = fmaf(av, w.y, acc.y); \
    acc.z = fmaf(av, w.z, acc.z); acc.w = fmaf(av, w.w, acc.w); }
    ISTEP(x0.x, 0)  ISTEP(x0.y, 1)  ISTEP(x0.z, 2)  ISTEP(x0.w, 3)
    ISTEP(x1.x, 4)  ISTEP(x1.y, 5)  ISTEP(x1.z, 6)  ISTEP(x1.w, 7)
    ISTEP(x2.x, 8)  ISTEP(x2.y, 9)  ISTEP(x2.z, 10) ISTEP(x2.w, 11)
    ISTEP(x3.x, 12) ISTEP(x3.y, 13) ISTEP(x3.z, 14) ISTEP(x3.w, 15)
#undef ISTEP
    ((float4*)(g_h0 + (size_t)n * HDIM))[g] = acc;
}

// ------ single-pass scan (decoupled lookback); also cursor init + g_cnt -------
__global__ void __launch_bounds__(SCAN_BLK) scan_lb(const int* __restrict__ batch) {
    __shared__ int wsum[SCAN_BLK / 32];
    __shared__ int sExcl;
    int bid = blockIdx.x;
    int d = bid * SCAN_BLK + threadIdx.x;
    int v = (d < N_NODES) ? g_deg[d] : 0;
    int lane = threadIdx.x & 31, w = threadIdx.x >> 5;

    int inc = v;
#pragma unroll
    for (int o = 1; o < 32; o <<= 1) {
        int t = __shfl_up_sync(0xffffffffu, inc, o);
        if (lane >= o) inc += t;
    }
    if (lane == 31) wsum[w] = inc;
    __syncthreads();
    if (w == 0) {
        int s = (lane < SCAN_BLK / 32) ? wsum[lane] : 0;
#pragma unroll
        for (int o = 1; o < 16; o <<= 1) {
            int t = __shfl_up_sync(0xffffffffu, s, o);
            if (lane >= o) s += t;
        }
        if (lane < SCAN_BLK / 32) wsum[lane] = s;
    }
    __syncthreads();
    int base = (w > 0) ? wsum[w - 1] : 0;
    int total = wsum[SCAN_BLK / 32 - 1];

    if (threadIdx.x == 0) {
        ull pub = (bid == 0) ? (FLAG_INC | (unsigned)total)
                             : (FLAG_AGG | (unsigned)total);
        __threadfence();
        atomicExch(&g_lb[bid], pub);
        if (bid == 0) sExcl = 0;
    }
    if (bid > 0 && w == 0) {
        int excl = 0;
        int offset = bid - 1;
        while (true) {
            int idx = offset - lane;
            ull val = (idx >= 0) ? ld_cg64(&g_lb[idx]) : FLAG_INC;
            while (__any_sync(0xffffffffu, val == 0ull))
                val = (idx >= 0) ? ld_cg64(&g_lb[idx]) : FLAG_INC;
            unsigned f2 = __ballot_sync(0xffffffffu, (val & FLAG_INC) != 0ull);
            int cv = (int)(unsigned)(val & 0xffffffffull);
            if (f2) {
                int first = __ffs(f2) - 1;
                int contrib = (lane <= first) ? cv : 0;
#pragma unroll
                for (int o = 16; o; o >>= 1) contrib += __shfl_xor_sync(0xffffffffu, contrib, o);
                excl += contrib;
                break;
            } else {
                int contrib = cv;
#pragma unroll
                for (int o = 16; o; o >>= 1) contrib += __shfl_xor_sync(0xffffffffu, contrib, o);
                excl += contrib;
                offset -= 32;
            }
        }
        if (lane == 0) {
            sExcl = excl;
            __threadfence();
            atomicExch(&g_lb[bid], FLAG_INC | (unsigned)(excl + total));
        }
    }
    __syncthreads();

    int bg = (d < N_NODES) ? __ldg(batch + d) : -1;
    if (d < N_NODES) {
        int o = sExcl + base + inc - v;
        g_off[d] = o;
        g_cursor[d] = o;
    }
    unsigned m = __match_any_sync(0xffffffffu, bg);
    if (bg >= 0 && (int)(__ffs(m) - 1) == lane)
        atomicAdd(&g_cnt[bg], (float)__popc(m));
}

// ----- project + scatter: ea_p[pos] = half2(edge_attr[e] @ eW + eb), dst-sorted
__global__ void __launch_bounds__(256) project_scatter(const float* __restrict__ edge_attr,
                                                       const int* __restrict__ esrc,
                                                       const int* __restrict__ edst,
                                                       const float* __restrict__ eW,
                                                       const float* __restrict__ eb) {
    int lane = threadIdx.x & 31;
    int w = threadIdx.x >> 5;
    int ebase = (blockIdx.x * 8 + w) * 8;     // grid = N_EDGES/64 = 25000 exact

    ull W0 = __ldg((const ull*)(eW + 0 * 64) + lane);
    ull W1 = __ldg((const ull*)(eW + 1 * 64) + lane);
    ull W2 = __ldg((const ull*)(eW + 2 * 64) + lane);
    ull W3 = __ldg((const ull*)(eW + 3 * 64) + lane);
    ull W4 = __ldg((const ull*)(eW + 4 * 64) + lane);
    ull W5 = __ldg((const ull*)(eW + 5 * 64) + lane);
    ull W6 = __ldg((const ull*)(eW + 6 * 64) + lane);
    ull W7 = __ldg((const ull*)(eW + 7 * 64) + lane);
    ull BB = __ldg((const ull*)eb + lane);

    int mysrc = 0, mypos = 0;
    if (lane < 8) {
        int e = ebase + lane;
        mysrc = __ldg(esrc + e);
        int d = __ldg(edst + e);
        mypos = atomicAdd(&g_cursor[d], 1);
    }

#pragma unroll
    for (int j = 0; j < 8; j++) {
        const float4* ap = (const float4*)(edge_attr + (size_t)(ebase + j) * 8);
        float4 a0 = __ldg(ap), a1 = __ldg(ap + 1);
        ull E = fma2_3(splat(a0.x), W0, BB);
        fma2(E, splat(a0.y), W1);
        fma2(E, splat(a0.z), W2);
        fma2(E, splat(a0.w), W3);
        fma2(E, splat(a1.x), W4);
        fma2(E, splat(a1.y), W5);
        fma2(E, splat(a1.z), W6);
        fma2(E, splat(a1.w), W7);
        float t0, t1; unpack2(t0, t1, E);
        __half2 hh = __floats2half2_rn(t0, t1);
        int pos = __shfl_sync(0xffffffffu, mypos, j);
        g_ea_p[(size_t)pos * 32 + lane] = *(unsigned*)&hh;
    }
    if (lane < 8) g_src_s[mypos] = mysrc;
}

// ---- per-dst aggregation: warp/dst, lane-split edge pairs (R9 version) --------
__global__ void __launch_bounds__(256) agg_pass(int cur) {
    int lane = threadIdx.x & 31;
    int half = lane >> 4;
    int fl = lane & 15;
    int d = blockIdx.x * 8 + (threadIdx.x >> 5);   // grid 12500 exact
    const float* h = cur ? g_h1 : g_h0;
    const ull* eap = (const ull*)g_ea_p;

    const ull L2E2 = splat(LOG2E);
    const ull C2   = splat(-SHL2);

    int start = g_off[d];
    int end = start + g_deg[d];
    ull DEN0 = 0ull, DEN1 = 0ull, NUM0 = 0ull, NUM1 = 0ull;

#define PBODY(EAu, HA, HB) { \
    unsigned lo_ = (unsigned)(EAu), hi_ = (unsigned)((EAu) >> 32); \
    float2 ea0 = __half22float2(*(__half2*)&lo_); \
    float2 ea1 = __half22float2(*(__half2*)&hi_); \
    ull E0 = add2(pack2(ea0.x, ea0.y), (HA)); \
    ull E1 = add2(pack2(ea1.x, ea1.y), (HB)); \
    float t0, t1, t2, t3; unpack2(t0, t1, E0); unpack2(t2, t3, E1); \
    float m0 = fmaxf(t0, 0.f) + EPSV, m1 = fmaxf(t1, 0.f) + EPSV; \
    float m2 = fmaxf(t2, 0.f) + EPSV, m3 = fmaxf(t3, 0.f) + EPSV; \
    ull M0 = pack2(m0, m1), M1 = pack2(m2, m3); \
    ull A0 = fma2_3(M0, L2E2, C2), A1 = fma2_3(M1, L2E2, C2); \
    float a0v, a1v, a2v, a3v; unpack2(a0v, a1v, A0); unpack2(a2v, a3v, A1); \
    ull X0 = pack2(exp2f(a0v), exp2f(a1v)); \
    ull X1 = pack2(exp2f(a2v), exp2f(a3v)); \
    DEN0 = add2(DEN0, X0); DEN1 = add2(DEN1, X1); \
    fma2(NUM0, M0, X0); fma2(NUM1, M1, X1); }

    int i = start;
    for (; i + 4 <= end; i += 4) {
        int sA = __ldg(g_src_s + i + half);
        int sB = __ldg(g_src_s + i + 2 + half);
        ull EA0 = __ldg(eap + (size_t)(i + half) * 16 + fl);
        ull EA1 = __ldg(eap + (size_t)(i + 2 + half) * 16 + fl);
        ulonglong2 HA = __ldg((const ulonglong2*)(h + (size_t)sA * HDIM + 4 * fl));
        ulonglong2 HB = __ldg((const ulonglong2*)(h + (size_t)sB * HDIM + 4 * fl));
        PBODY(EA0, HA.x, HA.y)
        PBODY(EA1, HB.x, HB.y)
    }
    for (; i + 2 <= end; i += 2) {
        int s = __ldg(g_src_s + i + half);
        ull EA = __ldg(eap + (size_t)(i + half) * 16 + fl);
        ulonglong2 HV = __ldg((const ulonglong2*)(h + (size_t)s * HDIM + 4 * fl));
        PBODY(EA, HV.x, HV.y)
    }
    if (i < end) {
        int s = __ldg(g_src_s + i);
        ull EA = __ldg(eap + (size_t)i * 16 + fl);
        ulonglong2 HV = __ldg((const ulonglong2*)(h + (size_t)s * HDIM + 4 * fl));
        if (half == 0) { PBODY(EA, HV.x, HV.y) }
    }
#undef PBODY

    DEN0 = add2(DEN0, __shfl_xor_sync(0xffffffffu, DEN0, 16));
    DEN1 = add2(DEN1, __shfl_xor_sync(0xffffffffu, DEN1, 16));
    NUM0 = add2(NUM0, __shfl_xor_sync(0xffffffffu, NUM0, 16));
    NUM1 = add2(NUM1, __shfl_xor_sync(0xffffffffu, NUM1, 16));

    if (half == 0) {
        float d0, d1, d2, d3, n0, n1, n2, n3;
        unpack2(d0, d1, DEN0); unpack2(d2, d3, DEN1);
        unpack2(n0, n1, NUM0); unpack2(n2, n3, NUM1);
        float4 o = make_float4(n0 / fmaxf(d0, 1e-16f), n1 / fmaxf(d1, 1e-16f),
                               n2 / fmaxf(d2, 1e-16f), n3 / fmaxf(d3, 1e-16f));
        *(float4*)(g_agg + (size_t)d * HDIM + 4 * fl) = o;
    }
}

// ---- node MLP v3: W1 staged in two 4K halves -> smem 68608B -> 3 CTAs/SM ------
// smem (floats): sH[128*68=8704] | union{ sX[64*68=4352] + sW1h[4096] , sW2[8192] }
#define SX_STRIDE 68
#define SH_STRIDE 68
#define SMEM_FLOATS (8704 + 4352 + 4096)   // 17152 floats = 68608 bytes

__global__ void __launch_bounds__(256, 3) node_mlp(int cur, int last,
                                                   const float* __restrict__ W1,
                                                   const float* __restrict__ b1,
                                                   const float* __restrict__ W2,
                                                   const float* __restrict__ b2,
                                                   const int* __restrict__ batch) {
    extern __shared__ float sm[];
    float* sH   = sm;                 // [128][68]
    float* sX   = sm + 8704;          // [64][68]
    float* sW1h = sm + 8704 + 4352;   // [32][128] (half of W1 at a time)
    float* sW2  = sm + 8704;          // [128][64] phase-2 overlay

    int tid = threadIdx.x;
    int base = blockIdx.x * 64;
    const float* h_in  = cur ? g_h1 : g_h0;
    float*       h_out = cur ? g_h0 : g_h1;

    // stage W1 first half (k = 0..31)
    {
        const float4* w4 = (const float4*)W1;
        float4* s4 = (float4*)sW1h;
#pragma unroll
        for (int i = 0; i < 4; i++) s4[tid + i * 256] = w4[tid + i * 256];
    }
    for (int idx = tid; idx < 64 * 64; idx += 256) {
        int n = idx >> 6, f = idx & 63;
        int gn = base + n;
        float v = 0.0f;
        if (gn < N_NODES)
            v = h_in[(size_t)gn * HDIM + f] + g_agg[(size_t)gn * HDIM + f];
        sX[f * SX_STRIDE + n] = v;
    }
    __syncthreads();

    int nodeg = tid & 15;   // 4 nodes
    int hidg  = tid >> 4;   // 8 hidden = 4 packed pairs

    // ---- phase 1: hid = relu(x @ W1 + b1), packed f32x2, two k-halves ----
    ull acc[4][4];
    {
        float4 ba = *(const float4*)&b1[hidg * 8];
        float4 bbv = *(const float4*)&b1[hidg * 8 + 4];
        ull p0 = pack2(ba.x, ba.y), p1 = pack2(ba.z, ba.w);
        ull p2 = pack2(bbv.x, bbv.y), p3 = pack2(bbv.z, bbv.w);
#pragma unroll
        for (int n = 0; n < 4; n++) { acc[n][0] = p0; acc[n][1] = p1; acc[n][2] = p2; acc[n][3] = p3; }
    }
#pragma unroll 4
    for (int k = 0; k < 32; k++) {
        float4 xv = *(const float4*)&sX[k * SX_STRIDE + nodeg * 4];
        ulonglong2 wA = *(const ulonglong2*)&sW1h[k * 128 + hidg * 8];
        ulonglong2 wB = *(const ulonglong2*)&sW1h[k * 128 + hidg * 8 + 4];
        float xs[4] = { xv.x, xv.y, xv.z, xv.w };
#pragma unroll
        for (int n = 0; n < 4; n++) {
            ull xd = pack2(xs[n], xs[n]);
            fma2(acc[n][0], xd, wA.x);
            fma2(acc[n][1], xd, wA.y);
            fma2(acc[n][2], xd, wB.x);
            fma2(acc[n][3], xd, wB.y);
        }
    }
    __syncthreads();
    // stage W1 second half (k = 32..63)
    {
        const float4* w4 = (const float4*)W1 + 1024;
        float4* s4 = (float4*)sW1h;
#pragma unroll
        for (int i = 0; i < 4; i++) s4[tid + i * 256] = w4[tid + i * 256];
    }
    __syncthreads();
#pragma unroll 4
    for (int k = 0; k < 32; k++) {
        float4 xv = *(const float4*)&sX[(k + 32) * SX_STRIDE + nodeg * 4];
        ulonglong2 wA = *(const ulonglong2*)&sW1h[k * 128 + hidg * 8];
        ulonglong2 wB = *(const ulonglong2*)&sW1h[k * 128 + hidg * 8 + 4];
        float xs[4] = { xv.x, xv.y, xv.z, xv.w };
#pragma unroll
        for (int n = 0; n < 4; n++) {
            ull xd = pack2(xs[n], xs[n]);
            fma2(acc[n][0], xd, wA.x);
            fma2(acc[n][1], xd, wA.y);
            fma2(acc[n][2], xd, wB.x);
            fma2(acc[n][3], xd, wB.y);
        }
    }
#pragma unroll
    for (int p = 0; p < 4; p++) {
        float lo[4], hi[4];
#pragma unroll
        for (int n = 0; n < 4; n++) unpack2(lo[n], hi[n], acc[n][p]);
        *(float4*)&sH[(hidg * 8 + 2 * p) * SH_STRIDE + nodeg * 4] =
            make_float4(fmaxf(lo[0], 0.f), fmaxf(lo[1], 0.f), fmaxf(lo[2], 0.f), fmaxf(lo[3], 0.f));
        *(float4*)&sH[(hidg * 8 + 2 * p + 1) * SH_STRIDE + nodeg * 4] =
            make_float4(fmaxf(hi[0], 0.f), fmaxf(hi[1], 0.f), fmaxf(hi[2], 0.f), fmaxf(hi[3], 0.f));
    }
    __syncthreads();

    // stage W2 into overlay region (sX is dead now)
    {
        const float4* w4 = (const float4*)W2;
        float4* s4 = (float4*)sW2;
#pragma unroll
        for (int i = 0; i < 8; i++) s4[tid + i * 256] = w4[tid + i * 256];
    }
    __syncthreads();

    // ---- phase 2: out = relu(hid @ W2 + b2), packed f32x2 ----
    int outg = tid >> 4;
    ull a2[4][2];
    {
        float4 bv = *(const float4*)&b2[outg * 4];
        ull p0 = pack2(bv.x, bv.y), p1 = pack2(bv.z, bv.w);
#pragma unroll
        for (int n = 0; n < 4; n++) { a2[n][0] = p0; a2[n][1] = p1; }
    }
#pragma unroll 4
    for (int k = 0; k < 128; k++) {
        float4 hv = *(const float4*)&sH[k * SH_STRIDE + nodeg * 4];
        ulonglong2 wp = *(const ulonglong2*)&sW2[k * 64 + outg * 4];
        float hs[4] = { hv.x, hv.y, hv.z, hv.w };
#pragma unroll
        for (int n = 0; n < 4; n++) {
            ull xd = pack2(hs[n], hs[n]);
            fma2(a2[n][0], xd, wp.x);
            fma2(a2[n][1], xd, wp.y);
        }
    }
#pragma unroll
    for (int n = 0; n < 4; n++) {
        int gn = base + nodeg * 4 + n;
        if (gn < N_NODES) {
            float r0, r1, r2, r3;
            unpack2(r0, r1, a2[n][0]);
            unpack2(r2, r3, a2[n][1]);
            r0 = fmaxf(r0, 0.f); r1 = fmaxf(r1, 0.f);
            r2 = fmaxf(r2, 0.f); r3 = fmaxf(r3, 0.f);
            if (last) {
                int b = __ldg(batch + gn);
                red4(g_pool + (size_t)b * HDIM + outg * 4, r0, r1, r2, r3);
            } else {
                *(float4*)&h_out[(size_t)gn * HDIM + outg * 4] = make_float4(r0, r1, r2, r3);
            }
        }
    }
}

// --------- graph head (restores g_deg / g_lb invariants for next call) ---------
__global__ void __launch_bounds__(256) head_kernel(const float* __restrict__ graph_attr,
                                                   const float* __restrict__ d1W, const float* __restrict__ d1b,
                                                   const float* __restrict__ d2W, const float* __restrict__ d2b,
                                                   const float* __restrict__ oW,  const float* __restrict__ ob,
                                                   float* __restrict__ out) {
    int t = blockIdx.x * 256 + threadIdx.x;
    for (int i = t; i < N_NODES; i += (N_GRAPHS * 32)) g_deg[i] = 0;
    if (t < NSCAN) g_lb[t] = 0ull;

    int g = t >> 5, lane = t & 31;
    if (g >= N_GRAPHS) return;
    float cnt = fmaxf(g_cnt[g], 1.0f);
    float p0 = g_pool[g * HDIM + lane] / cnt;
    float p1 = g_pool[g * HDIM + 32 + lane] / cnt;
    float ga = (lane < 10) ? graph_attr[g * 10 + lane] : 0.0f;

    float a = d1b[lane];
#pragma unroll
    for (int k = 0; k < 32; k++) a = fmaf(__shfl_sync(0xffffffffu, p0, k), d1W[k * 32 + lane], a);
#pragma unroll
    for (int k = 0; k < 32; k++) a = fmaf(__shfl_sync(0xffffffffu, p1, k), d1W[(32 + k) * 32 + lane], a);
#pragma unroll
    for (int k = 0; k < 10; k++) a = fmaf(__shfl_sync(0xffffffffu, ga, k), d1W[(64 + k) * 32 + lane], a);
    a = fmaxf(a, 0.0f);

    float bsum = d2b[lane];
#pragma unroll
    for (int k = 0; k < 32; k++) bsum = fmaf(__shfl_sync(0xffffffffu, a, k), d2W[k * 32 + lane], bsum);
    bsum = fmaxf(bsum, 0.0f);

    float v = bsum * oW[lane];
#pragma unroll
    for (int s = 16; s > 0; s >>= 1) v += __shfl_xor_sync(0xffffffffu, v, s);
    if (lane == 0) out[g] = 1.0f / (1.0f + expf(-(v + ob[0])));
}

// ---------------- launch -------------------------------------------------------
extern "C" void kernel_launch(void* const* d_in, const int* in_sizes, int n_in,
                              void* d_out, int out_size) {
    const float* x          = (const float*)d_in[0];
    const float* edge_attr  = (const float*)d_in[1];
    const float* graph_attr = (const float*)d_in[2];
    const int*   edge_index = (const int*)d_in[3];
    const int*   batch      = (const int*)d_in[4];
    const float* node_W     = (const float*)d_in[5];
    const float* node_b     = (const float*)d_in[6];
    const float* edge_W     = (const float*)d_in[7];
    const float* edge_b     = (const float*)d_in[8];
    const float* cW1[3] = { (const float*)d_in[9],  (const float*)d_in[13], (const float*)d_in[17] };
    const float* cb1[3] = { (const float*)d_in[10], (const float*)d_in[14], (const float*)d_in[18] };
    const float* cW2[3] = { (const float*)d_in[11], (const float*)d_in[15], (const float*)d_in[19] };
    const float* cb2[3] = { (const float*)d_in[12], (const float*)d_in[16], (const float*)d_in[20] };
    const float* d1W = (const float*)d_in[21];
    const float* d1b = (const float*)d_in[22];
    const float* d2W = (const float*)d_in[23];
    const float* d2b = (const float*)d_in[24];
    const float* oW  = (const float*)d_in[25];
    const float* ob  = (const float*)d_in[26];
    const int* esrc = edge_index;
    const int* edst = edge_index + N_EDGES;
    float* out = (float*)d_out;

    const int SMEM_MLP = SMEM_FLOATS * 4;   // 68608 bytes
    cudaFuncSetAttribute((const void*)node_mlp,
                         cudaFuncAttributeMaxDynamicSharedMemorySize, SMEM_MLP);

    // 1: proj + hist + zeroing
    input_proj<<<N_EDGES / 256, 256>>>(x, node_W, node_b, edst);
    // 2: single-pass scan (+cursor init, g_cnt)
    scan_lb<<<NSCAN, SCAN_BLK>>>(batch);
    // 3: project ea once (fp16) + scatter to dst order
    project_scatter<<<N_EDGES / 64, 256>>>(edge_attr, esrc, edst, edge_W, edge_b);

    int cur = 0;
    const int NBLK_MLP = (N_NODES + 63) / 64;
    for (int c = 0; c < 3; c++) {
        // c==0: launch #4 = agg_pass (control: expect ~86 us)
        agg_pass<<<N_NODES / 8, 256>>>(cur);
        node_mlp<<<NBLK_MLP, 256, SMEM_MLP>>>(cur, (c == 2) ? 1 : 0,
                                              cW1[c], cb1[c], cW2[c], cb2[c], batch);
        cur ^= 1;
    }

    head_kernel<<<(N_GRAPHS * 32) / 256, 256>>>(graph_attr, d1W, d1b, d2W, d2b, oW, ob, out);
}